// round 10
// baseline (speedup 1.0000x reference)
#include <cuda_runtime.h>
#include <math.h>

// ---------------------------------------------------------------------------
// Problem constants
// ---------------------------------------------------------------------------
#define Bc   4
#define Lc   2048
#define DINc 80
#define Dc   128
#define Hc   16
#define DHc  8
#define DFFc 128
#define WINc 64
#define Mrows (Bc * Lc)        // 8192

// ---------------------------------------------------------------------------
// Scratch (device globals: allocation-free)
// ---------------------------------------------------------------------------
__device__ float g_h  [Mrows * Dc];        // post conv+bn+pe
__device__ float g_q  [Bc * Hc * Lc * DHc];
__device__ float g_kb [Bc * Hc * Lc * DHc];
__device__ float g_vb [Bc * Hc * Lc * DHc];
__device__ float g_ctx[Mrows * Dc];
__device__ float g_ao [Mrows * Dc];
__device__ float g_f  [Mrows * DFFc];
__device__ float g_g2 [Mrows * Dc];
__device__ float g_pe [Lc * Dc];

// ---------------------------------------------------------------------------
// Positional encoding table: pe[l][d], d pair j=d>>1, even->sin, odd->cos,
// divisor 10000^(j/128)  (faithful to the reference's exponent j/d)
// ---------------------------------------------------------------------------
__global__ void pe_kernel(float* __restrict__ pe) {
    int l = blockIdx.x;
    int d = threadIdx.x;
    int j = d >> 1;
    float pj  = powf(10000.0f, (float)j / 128.0f);
    float ang = (float)l / pj;
    pe[l * Dc + d] = (d & 1) ? cosf(ang) : sinf(ang);
}

// ---------------------------------------------------------------------------
// Tiled SGEMM: C[M,N] = A[M,K] @ W[N,K]^T (+ bias, + mode-specific epilogue)
// BM=BN=64, BK=64 chunked, 256 threads, 4x4 micro-tile per thread.
// Smem tiles stored K-major-transposed so inner loop is float4 LDS.
// MODE: 0 = bias        1 = bias+relu
//       2 = relu -> batchnorm -> +pe   (e0=g, e1=b, e2=rm, e3=rv, e4=pe)
//       3 = qkv scatter to [B,H,L,DH]  (C=q, o1=k, o2=v)
// ---------------------------------------------------------------------------
template <int MODE>
__global__ void __launch_bounds__(256)
gemm_k(const float* __restrict__ A, const float* __restrict__ W,
       const float* __restrict__ bias, float* __restrict__ C,
       int M, int N, int K,
       const float* __restrict__ e0, const float* __restrict__ e1,
       const float* __restrict__ e2, const float* __restrict__ e3,
       const float* __restrict__ e4,
       float* __restrict__ o1, float* __restrict__ o2)
{
    __shared__ float As[64][64];   // As[k][m]
    __shared__ float Ws[64][64];   // Ws[k][n]

    const int tid  = threadIdx.x;
    const int tx   = tid & 15;     // col group
    const int ty   = tid >> 4;     // row group
    const int row0 = blockIdx.y * 64;
    const int col0 = blockIdx.x * 64;

    float acc[4][4] = {};

    for (int k0 = 0; k0 < K; k0 += 64) {
        const int kc = min(64, K - k0);

        for (int idx = tid; idx < 64 * kc; idx += 256) {
            int m  = idx / kc;
            int kk = idx - m * kc;
            As[kk][m] = A[(size_t)(row0 + m) * K + k0 + kk];
        }
        for (int idx = tid; idx < 64 * kc; idx += 256) {
            int n  = idx / kc;
            int kk = idx - n * kc;
            Ws[kk][n] = (col0 + n < N) ? W[(size_t)(col0 + n) * K + k0 + kk] : 0.0f;
        }
        __syncthreads();

        #pragma unroll 8
        for (int kk = 0; kk < kc; kk++) {
            float4 a4 = *(const float4*)&As[kk][ty * 4];
            float4 w4 = *(const float4*)&Ws[kk][tx * 4];
            float av[4] = {a4.x, a4.y, a4.z, a4.w};
            float wv[4] = {w4.x, w4.y, w4.z, w4.w};
            #pragma unroll
            for (int i = 0; i < 4; i++)
                #pragma unroll
                for (int j = 0; j < 4; j++)
                    acc[i][j] += av[i] * wv[j];
        }
        __syncthreads();
    }

    #pragma unroll
    for (int i = 0; i < 4; i++) {
        const int m = row0 + ty * 4 + i;
        #pragma unroll
        for (int j = 0; j < 4; j++) {
            const int col = col0 + tx * 4 + j;
            if (col >= N) continue;
            float v = acc[i][j] + bias[col];
            if (MODE == 0) {
                C[(size_t)m * N + col] = v;
            } else if (MODE == 1) {
                C[(size_t)m * N + col] = fmaxf(v, 0.0f);
            } else if (MODE == 2) {
                v = fmaxf(v, 0.0f);
                v = (v - e2[col]) * (e0[col] * rsqrtf(e3[col] + 1e-5f)) + e1[col];
                int l = m & (Lc - 1);
                v += e4[l * Dc + col];
                C[(size_t)m * Dc + col] = v;
            } else {  // MODE 3: qkv scatter
                int b     = m >> 11;          // m / L
                int l     = m & (Lc - 1);
                int which = col >> 7;         // 0:q 1:k 2:v
                int d     = col & 127;
                int hh    = d >> 3;
                int dh    = d & 7;
                float* dst = (which == 0) ? C : ((which == 1) ? o1 : o2);
                dst[(((size_t)(b * Hc + hh)) * Lc + l) * DHc + dh] = v;
            }
        }
    }
}

// ---------------------------------------------------------------------------
// Local-window attention: one warp per (b,h,q).
// Window: keys j with 1 <= |j-q| <= 64 (diagonal EXCLUDED), clipped to [0,L).
// q/k/v layout: [B,H,L,8] contiguous. ctx written as [B,L,H*8] = [B,L,128].
// ---------------------------------------------------------------------------
__global__ void __launch_bounds__(256)
attn_kernel(const float* __restrict__ Q, const float* __restrict__ Kb,
            const float* __restrict__ Vb, float* __restrict__ ctx)
{
    const int warp = blockIdx.x * (blockDim.x >> 5) + (threadIdx.x >> 5);
    const int lane = threadIdx.x & 31;
    const int qpos = warp & (Lc - 1);
    const int bh   = warp >> 11;                 // b*H + h, 0..63

    const float* qp = Q  + ((size_t)bh * Lc + qpos) * DHc;
    const float* kp = Kb + (size_t)bh * Lc * DHc;
    const float* vp = Vb + (size_t)bh * Lc * DHc;

    const float4 q0 = *(const float4*)qp;
    const float4 q1 = *(const float4*)(qp + 4);

    int lo = qpos - WINc; if (lo < 0) lo = 0;
    int hi = qpos + WINc; if (hi > Lc - 1) hi = Lc - 1;

    const float scale = 0.35355339059327373f;    // 1/sqrt(8)

    float sc[5];
    float mx = -INFINITY;
    #pragma unroll
    for (int i = 0; i < 5; i++) {
        const int j = lo + lane + 32 * i;
        float s = -INFINITY;
        if (j <= hi && j != qpos) {
            const float4* kr = (const float4*)(kp + (size_t)j * DHc);
            float4 k0 = kr[0], k1 = kr[1];
            s = q0.x * k0.x + q0.y * k0.y + q0.z * k0.z + q0.w * k0.w
              + q1.x * k1.x + q1.y * k1.y + q1.z * k1.z + q1.w * k1.w;
            s *= scale;
            mx = fmaxf(mx, s);
        }
        sc[i] = s;
    }
    #pragma unroll
    for (int o = 16; o; o >>= 1)
        mx = fmaxf(mx, __shfl_xor_sync(0xffffffffu, mx, o));

    float sum = 0.0f;
    float c[8] = {0, 0, 0, 0, 0, 0, 0, 0};
    #pragma unroll
    for (int i = 0; i < 5; i++) {
        const int j = lo + lane + 32 * i;
        if (sc[i] != -INFINITY) {
            const float p = __expf(sc[i] - mx);
            sum += p;
            const float4* vr = (const float4*)(vp + (size_t)j * DHc);
            float4 v0 = vr[0], v1 = vr[1];
            c[0] += p * v0.x; c[1] += p * v0.y; c[2] += p * v0.z; c[3] += p * v0.w;
            c[4] += p * v1.x; c[5] += p * v1.y; c[6] += p * v1.z; c[7] += p * v1.w;
        }
    }
    #pragma unroll
    for (int o = 16; o; o >>= 1) {
        sum += __shfl_xor_sync(0xffffffffu, sum, o);
        #pragma unroll
        for (int d = 0; d < 8; d++)
            c[d] += __shfl_xor_sync(0xffffffffu, c[d], o);
    }

    if (lane < 8) {
        const float inv = 1.0f / sum;
        float val = 0.0f;
        #pragma unroll
        for (int d = 0; d < 8; d++)
            if (lane == d) val = c[d];
        const int hh = bh & (Hc - 1);
        const int b  = bh >> 4;
        ctx[((size_t)(b * Lc + qpos)) * Dc + hh * DHc + lane] = val * inv;
    }
}

// ---------------------------------------------------------------------------
// Launch
// ---------------------------------------------------------------------------
extern "C" void kernel_launch(void* const* d_in, const int* in_sizes, int n_in,
                              void* d_out, int out_size)
{
    const float* x         = (const float*)d_in[0];
    const float* conv_w    = (const float*)d_in[1];
    const float* conv_b    = (const float*)d_in[2];
    const float* bn_g      = (const float*)d_in[3];
    const float* bn_b      = (const float*)d_in[4];
    const float* bn_rm     = (const float*)d_in[5];
    const float* bn_rv     = (const float*)d_in[6];
    const float* in_proj_w = (const float*)d_in[7];
    const float* in_proj_b = (const float*)d_in[8];
    const float* out_w     = (const float*)d_in[9];
    const float* out_b     = (const float*)d_in[10];
    const float* ff_w1     = (const float*)d_in[11];
    const float* ff_b1     = (const float*)d_in[12];
    const float* ff_w2     = (const float*)d_in[13];
    const float* ff_b2     = (const float*)d_in[14];
    const float* fc_w      = (const float*)d_in[15];
    const float* fc_b      = (const float*)d_in[16];
    float* out = (float*)d_out;

    float *h, *q, *kb, *vb, *ctx, *ao, *f, *g2, *pe;
    cudaGetSymbolAddress((void**)&h,   g_h);
    cudaGetSymbolAddress((void**)&q,   g_q);
    cudaGetSymbolAddress((void**)&kb,  g_kb);
    cudaGetSymbolAddress((void**)&vb,  g_vb);
    cudaGetSymbolAddress((void**)&ctx, g_ctx);
    cudaGetSymbolAddress((void**)&ao,  g_ao);
    cudaGetSymbolAddress((void**)&f,   g_f);
    cudaGetSymbolAddress((void**)&g2,  g_g2);
    cudaGetSymbolAddress((void**)&pe,  g_pe);

    // 0) positional encoding table
    pe_kernel<<<Lc, Dc>>>(pe);

    // 1) conv(k=1) + relu + batchnorm + pe : [8192,80]x[128,80]^T -> h
    gemm_k<2><<<dim3(2, Mrows / 64), 256>>>(x, conv_w, conv_b, h,
        Mrows, Dc, DINc, bn_g, bn_b, bn_rm, bn_rv, pe, nullptr, nullptr);

    // 2) qkv projection with scatter to [B,H,L,8]
    gemm_k<3><<<dim3(6, Mrows / 64), 256>>>(h, in_proj_w, in_proj_b, q,
        Mrows, 3 * Dc, Dc, nullptr, nullptr, nullptr, nullptr, nullptr, kb, vb);

    // 3) local-window attention -> ctx [B,L,128]
    attn_kernel<<<(Bc * Hc * Lc) / 8, 256>>>(q, kb, vb, ctx);

    // 4) out projection
    gemm_k<0><<<dim3(2, Mrows / 64), 256>>>(ctx, out_w, out_b, ao,
        Mrows, Dc, Dc, nullptr, nullptr, nullptr, nullptr, nullptr, nullptr, nullptr);

    // 5) ffn layer 1 (relu)
    gemm_k<1><<<dim3(2, Mrows / 64), 256>>>(ao, ff_w1, ff_b1, f,
        Mrows, DFFc, Dc, nullptr, nullptr, nullptr, nullptr, nullptr, nullptr, nullptr);

    // 6) ffn layer 2
    gemm_k<0><<<dim3(2, Mrows / 64), 256>>>(f, ff_w2, ff_b2, g2,
        Mrows, Dc, DFFc, nullptr, nullptr, nullptr, nullptr, nullptr, nullptr, nullptr);

    // 7) final head -> d_out [8192,80]
    gemm_k<0><<<dim3(2, Mrows / 64), 256>>>(g2, fc_w, fc_b, out,
        Mrows, DINc, Dc, nullptr, nullptr, nullptr, nullptr, nullptr, nullptr, nullptr);
}

// round 11
// speedup vs baseline: 1.0146x; 1.0146x over previous
#include <cuda_runtime.h>
#include <math.h>

// ---------------------------------------------------------------------------
// Problem constants
// ---------------------------------------------------------------------------
#define Bc   4
#define Lc   2048
#define DINc 80
#define Dc   128
#define Hc   16
#define DHc  8
#define DFFc 128
#define WINc 64
#define Mrows (Bc * Lc)        // 8192

// ---------------------------------------------------------------------------
// Scratch (device globals: allocation-free)
// ---------------------------------------------------------------------------
__device__ float g_h  [Mrows * Dc];        // post conv+bn+pe
__device__ float g_q  [Bc * Hc * Lc * DHc];
__device__ float g_kb [Bc * Hc * Lc * DHc];
__device__ float g_vb [Bc * Hc * Lc * DHc];
__device__ float g_ctx[Mrows * Dc];
__device__ float g_ao [Mrows * Dc];
__device__ float g_f  [Mrows * DFFc];
__device__ float g_g2 [Mrows * Dc];
__device__ float g_pe [Lc * Dc];

// ---------------------------------------------------------------------------
// Positional encoding table: pe[l][d], d pair j=d>>1, even->sin, odd->cos,
// divisor 10000^(j/128)  (faithful to the reference's exponent j/d)
// ---------------------------------------------------------------------------
__global__ void pe_kernel(float* __restrict__ pe) {
    int l = blockIdx.x;
    int d = threadIdx.x;
    int j = d >> 1;
    float pj  = powf(10000.0f, (float)j / 128.0f);
    float ang = (float)l / pj;
    pe[l * Dc + d] = (d & 1) ? cosf(ang) : sinf(ang);
}

// ---------------------------------------------------------------------------
// Tiled SGEMM: C[M,N] = A[M,K] @ W[N,K]^T (+ bias, + mode-specific epilogue)
// BM=BN=64, BK=64 chunked, 256 threads, 4x4 micro-tile per thread.
// Smem tiles stored K-major-transposed so inner loop is float4 LDS.
// MODE: 0 = bias        1 = bias+relu
//       2 = relu -> batchnorm -> +pe   (e0=g, e1=b, e2=rm, e3=rv, e4=pe)
//       3 = qkv scatter to [B,H,L,DH]  (C=q, o1=k, o2=v)
// ---------------------------------------------------------------------------
template <int MODE>
__global__ void __launch_bounds__(256)
gemm_k(const float* __restrict__ A, const float* __restrict__ W,
       const float* __restrict__ bias, float* __restrict__ C,
       int M, int N, int K,
       const float* __restrict__ e0, const float* __restrict__ e1,
       const float* __restrict__ e2, const float* __restrict__ e3,
       const float* __restrict__ e4,
       float* __restrict__ o1, float* __restrict__ o2)
{
    __shared__ float As[64][64];   // As[k][m]
    __shared__ float Ws[64][64];   // Ws[k][n]

    const int tid  = threadIdx.x;
    const int tx   = tid & 15;     // col group
    const int ty   = tid >> 4;     // row group
    const int row0 = blockIdx.y * 64;
    const int col0 = blockIdx.x * 64;

    float acc[4][4] = {};

    for (int k0 = 0; k0 < K; k0 += 64) {
        const int kc = min(64, K - k0);

        for (int idx = tid; idx < 64 * kc; idx += 256) {
            int m  = idx / kc;
            int kk = idx - m * kc;
            As[kk][m] = A[(size_t)(row0 + m) * K + k0 + kk];
        }
        for (int idx = tid; idx < 64 * kc; idx += 256) {
            int n  = idx / kc;
            int kk = idx - n * kc;
            Ws[kk][n] = (col0 + n < N) ? W[(size_t)(col0 + n) * K + k0 + kk] : 0.0f;
        }
        __syncthreads();

        #pragma unroll 8
        for (int kk = 0; kk < kc; kk++) {
            float4 a4 = *(const float4*)&As[kk][ty * 4];
            float4 w4 = *(const float4*)&Ws[kk][tx * 4];
            float av[4] = {a4.x, a4.y, a4.z, a4.w};
            float wv[4] = {w4.x, w4.y, w4.z, w4.w};
            #pragma unroll
            for (int i = 0; i < 4; i++)
                #pragma unroll
                for (int j = 0; j < 4; j++)
                    acc[i][j] += av[i] * wv[j];
        }
        __syncthreads();
    }

    #pragma unroll
    for (int i = 0; i < 4; i++) {
        const int m = row0 + ty * 4 + i;
        #pragma unroll
        for (int j = 0; j < 4; j++) {
            const int col = col0 + tx * 4 + j;
            if (col >= N) continue;
            float v = acc[i][j] + bias[col];
            if (MODE == 0) {
                C[(size_t)m * N + col] = v;
            } else if (MODE == 1) {
                C[(size_t)m * N + col] = fmaxf(v, 0.0f);
            } else if (MODE == 2) {
                v = fmaxf(v, 0.0f);
                v = (v - e2[col]) * (e0[col] * rsqrtf(e3[col] + 1e-5f)) + e1[col];
                int l = m & (Lc - 1);
                v += e4[l * Dc + col];
                C[(size_t)m * Dc + col] = v;
            } else {  // MODE 3: qkv scatter
                int b     = m >> 11;          // m / L
                int l     = m & (Lc - 1);
                int which = col >> 7;         // 0:q 1:k 2:v
                int d     = col & 127;
                int hh    = d >> 3;
                int dh    = d & 7;
                float* dst = (which == 0) ? C : ((which == 1) ? o1 : o2);
                dst[(((size_t)(b * Hc + hh)) * Lc + l) * DHc + dh] = v;
            }
        }
    }
}

// ---------------------------------------------------------------------------
// Local-window attention: one warp per (b,h,q).
// Window: keys j with 1 <= |j-q| <= 64 (diagonal EXCLUDED), clipped to [0,L).
// q/k/v layout: [B,H,L,8] contiguous. ctx written as [B,L,H*8] = [B,L,128].
// ---------------------------------------------------------------------------
__global__ void __launch_bounds__(256)
attn_kernel(const float* __restrict__ Q, const float* __restrict__ Kb,
            const float* __restrict__ Vb, float* __restrict__ ctx)
{
    const int warp = blockIdx.x * (blockDim.x >> 5) + (threadIdx.x >> 5);
    const int lane = threadIdx.x & 31;
    const int qpos = warp & (Lc - 1);
    const int bh   = warp >> 11;                 // b*H + h, 0..63

    const float* qp = Q  + ((size_t)bh * Lc + qpos) * DHc;
    const float* kp = Kb + (size_t)bh * Lc * DHc;
    const float* vp = Vb + (size_t)bh * Lc * DHc;

    const float4 q0 = *(const float4*)qp;
    const float4 q1 = *(const float4*)(qp + 4);

    int lo = qpos - WINc; if (lo < 0) lo = 0;
    int hi = qpos + WINc; if (hi > Lc - 1) hi = Lc - 1;

    const float scale = 0.35355339059327373f;    // 1/sqrt(8)

    float sc[5];
    float mx = -INFINITY;
    #pragma unroll
    for (int i = 0; i < 5; i++) {
        const int j = lo + lane + 32 * i;
        float s = -INFINITY;
        if (j <= hi && j != qpos) {
            const float4* kr = (const float4*)(kp + (size_t)j * DHc);
            float4 k0 = kr[0], k1 = kr[1];
            s = q0.x * k0.x + q0.y * k0.y + q0.z * k0.z + q0.w * k0.w
              + q1.x * k1.x + q1.y * k1.y + q1.z * k1.z + q1.w * k1.w;
            s *= scale;
            mx = fmaxf(mx, s);
        }
        sc[i] = s;
    }
    #pragma unroll
    for (int o = 16; o; o >>= 1)
        mx = fmaxf(mx, __shfl_xor_sync(0xffffffffu, mx, o));

    float sum = 0.0f;
    float c[8] = {0, 0, 0, 0, 0, 0, 0, 0};
    #pragma unroll
    for (int i = 0; i < 5; i++) {
        const int j = lo + lane + 32 * i;
        if (sc[i] != -INFINITY) {
            const float p = __expf(sc[i] - mx);
            sum += p;
            const float4* vr = (const float4*)(vp + (size_t)j * DHc);
            float4 v0 = vr[0], v1 = vr[1];
            c[0] += p * v0.x; c[1] += p * v0.y; c[2] += p * v0.z; c[3] += p * v0.w;
            c[4] += p * v1.x; c[5] += p * v1.y; c[6] += p * v1.z; c[7] += p * v1.w;
        }
    }
    #pragma unroll
    for (int o = 16; o; o >>= 1) {
        sum += __shfl_xor_sync(0xffffffffu, sum, o);
        #pragma unroll
        for (int d = 0; d < 8; d++)
            c[d] += __shfl_xor_sync(0xffffffffu, c[d], o);
    }

    if (lane < 8) {
        const float inv = 1.0f / sum;
        float val = 0.0f;
        #pragma unroll
        for (int d = 0; d < 8; d++)
            if (lane == d) val = c[d];
        const int hh = bh & (Hc - 1);
        const int b  = bh >> 4;
        ctx[((size_t)(b * Lc + qpos)) * Dc + hh * DHc + lane] = val * inv;
    }
}

// ---------------------------------------------------------------------------
// Launch
// ---------------------------------------------------------------------------
extern "C" void kernel_launch(void* const* d_in, const int* in_sizes, int n_in,
                              void* d_out, int out_size)
{
    const float* x         = (const float*)d_in[0];
    const float* conv_w    = (const float*)d_in[1];
    const float* conv_b    = (const float*)d_in[2];
    const float* bn_g      = (const float*)d_in[3];
    const float* bn_b      = (const float*)d_in[4];
    const float* bn_rm     = (const float*)d_in[5];
    const float* bn_rv     = (const float*)d_in[6];
    const float* in_proj_w = (const float*)d_in[7];
    const float* in_proj_b = (const float*)d_in[8];
    const float* out_w     = (const float*)d_in[9];
    const float* out_b     = (const float*)d_in[10];
    const float* ff_w1     = (const float*)d_in[11];
    const float* ff_b1     = (const float*)d_in[12];
    const float* ff_w2     = (const float*)d_in[13];
    const float* ff_b2     = (const float*)d_in[14];
    const float* fc_w      = (const float*)d_in[15];
    const float* fc_b      = (const float*)d_in[16];
    float* out = (float*)d_out;

    float *h, *q, *kb, *vb, *ctx, *ao, *f, *g2, *pe;
    cudaGetSymbolAddress((void**)&h,   g_h);
    cudaGetSymbolAddress((void**)&q,   g_q);
    cudaGetSymbolAddress((void**)&kb,  g_kb);
    cudaGetSymbolAddress((void**)&vb,  g_vb);
    cudaGetSymbolAddress((void**)&ctx, g_ctx);
    cudaGetSymbolAddress((void**)&ao,  g_ao);
    cudaGetSymbolAddress((void**)&f,   g_f);
    cudaGetSymbolAddress((void**)&g2,  g_g2);
    cudaGetSymbolAddress((void**)&pe,  g_pe);

    // 0) positional encoding table
    pe_kernel<<<Lc, Dc>>>(pe);

    // 1) conv(k=1) + relu + batchnorm + pe : [8192,80]x[128,80]^T -> h
    gemm_k<2><<<dim3(2, Mrows / 64), 256>>>(x, conv_w, conv_b, h,
        Mrows, Dc, DINc, bn_g, bn_b, bn_rm, bn_rv, pe, nullptr, nullptr);

    // 2) qkv projection with scatter to [B,H,L,8]
    gemm_k<3><<<dim3(6, Mrows / 64), 256>>>(h, in_proj_w, in_proj_b, q,
        Mrows, 3 * Dc, Dc, nullptr, nullptr, nullptr, nullptr, nullptr, kb, vb);

    // 3) local-window attention -> ctx [B,L,128]
    attn_kernel<<<(Bc * Hc * Lc) / 8, 256>>>(q, kb, vb, ctx);

    // 4) out projection
    gemm_k<0><<<dim3(2, Mrows / 64), 256>>>(ctx, out_w, out_b, ao,
        Mrows, Dc, Dc, nullptr, nullptr, nullptr, nullptr, nullptr, nullptr, nullptr);

    // 5) ffn layer 1 (relu)
    gemm_k<1><<<dim3(2, Mrows / 64), 256>>>(ao, ff_w1, ff_b1, f,
        Mrows, DFFc, Dc, nullptr, nullptr, nullptr, nullptr, nullptr, nullptr, nullptr);

    // 6) ffn layer 2
    gemm_k<0><<<dim3(2, Mrows / 64), 256>>>(f, ff_w2, ff_b2, g2,
        Mrows, Dc, DFFc, nullptr, nullptr, nullptr, nullptr, nullptr, nullptr, nullptr);

    // 7) final head -> d_out [8192,80]
    gemm_k<0><<<dim3(2, Mrows / 64), 256>>>(g2, fc_w, fc_b, out,
        Mrows, DINc, Dc, nullptr, nullptr, nullptr, nullptr, nullptr, nullptr, nullptr);
}